// round 5
// baseline (speedup 1.0000x reference)
#include <cuda_runtime.h>
#include <math.h>

// Problem constants
// B=8, S=1024, E=1024, H=16, D=64
#define BB 8
#define SS 1024
#define EE 1024
#define HH 16
#define DD 64
#define MM (BB * SS)          // 8192 rows for all GEMMs

// Scratch buffers (allocation-free rule: __device__ globals)
__device__ float g_q[MM * EE];
__device__ float g_k[MM * EE];
__device__ float g_v[MM * EE];
__device__ float g_attn[MM * EE];

// ---------------------------------------------------------------------------
// SGEMM: C[M,N] = A[M,K] @ B[K,N] (+ bias[N] if bias != nullptr)
// 128x128 tile, K-step 8, 256 threads, 8x8 micro-tile per thread.
// M % 128 == 0, N % 128 == 0, K % 8 == 0 (true for all our calls).
// ---------------------------------------------------------------------------
__global__ __launch_bounds__(256, 2)
void sgemm128(const float* __restrict__ A, const float* __restrict__ B,
              const float* __restrict__ bias, float* __restrict__ C,
              int M, int N, int K)
{
    __shared__ __align__(16) float As[8][128];
    __shared__ __align__(16) float Bs[8][128];

    const int tid = threadIdx.x;
    const int bm = blockIdx.y * 128;
    const int bn = blockIdx.x * 128;

    // micro-tile origin
    const int tr = (tid >> 4) << 3;   // 0..120
    const int tc = (tid & 15) << 3;   // 0..120

    // A tile load mapping: 128 rows x 8 cols, one float4 per thread
    const int arow = tid >> 1;
    const int acol = (tid & 1) << 2;
    // B tile load mapping: 8 rows x 128 cols, one float4 per thread
    const int brow = tid >> 5;
    const int bcol = (tid & 31) << 2;

    const float* Ap = A + (size_t)(bm + arow) * K + acol;
    const float* Bp = B + (size_t)brow * N + bn + bcol;

    float acc[8][8];
#pragma unroll
    for (int i = 0; i < 8; i++)
#pragma unroll
        for (int j = 0; j < 8; j++) acc[i][j] = 0.f;

    for (int k0 = 0; k0 < K; k0 += 8) {
        float4 av = *(const float4*)(Ap + k0);
        // transposed scalar stores (column of As) — scalar STS, alignment fine
        As[acol + 0][arow] = av.x;
        As[acol + 1][arow] = av.y;
        As[acol + 2][arow] = av.z;
        As[acol + 3][arow] = av.w;
        *(float4*)&Bs[brow][bcol] = *(const float4*)(Bp + (size_t)k0 * N);
        __syncthreads();

#pragma unroll
        for (int kk = 0; kk < 8; kk++) {
            float a[8], b[8];
            *(float4*)(a)     = *(const float4*)&As[kk][tr];
            *(float4*)(a + 4) = *(const float4*)&As[kk][tr + 4];
            *(float4*)(b)     = *(const float4*)&Bs[kk][tc];
            *(float4*)(b + 4) = *(const float4*)&Bs[kk][tc + 4];
#pragma unroll
            for (int i = 0; i < 8; i++)
#pragma unroll
                for (int j = 0; j < 8; j++)
                    acc[i][j] += a[i] * b[j];
        }
        __syncthreads();
    }

    float bb[8];
#pragma unroll
    for (int j = 0; j < 8; j++)
        bb[j] = bias ? bias[bn + tc + j] : 0.f;

#pragma unroll
    for (int i = 0; i < 8; i++) {
        float* crow = C + (size_t)(bm + tr + i) * N + bn + tc;
        float4 v0, v1;
        v0.x = acc[i][0] + bb[0]; v0.y = acc[i][1] + bb[1];
        v0.z = acc[i][2] + bb[2]; v0.w = acc[i][3] + bb[3];
        v1.x = acc[i][4] + bb[4]; v1.y = acc[i][5] + bb[5];
        v1.z = acc[i][6] + bb[6]; v1.w = acc[i][7] + bb[7];
        *(float4*)(crow)     = v0;
        *(float4*)(crow + 4) = v1;
    }
}

// ---------------------------------------------------------------------------
// Attention: per (b,h) head slab (contiguous [S=1024, D=64] thanks to the
// raw-reshape quirk), flash-style online softmax.
// grid = (S/8, B*H); block = 256 threads = 8 warps; one warp per query row.
// Each lane owns t = lane and t = lane+32 within a 64-wide t-chunk, and
// accumulates a full 64-wide O partial; warp butterfly reduces at the end.
//
// K/V tiles padded to 68 floats/row: 68*4 = 272 B, divisible by 16, so every
// float4 access is aligned; LDS.128 bank pattern (4*lane+4j) mod 32 is
// conflict-free within each 8-lane phase.
// ---------------------------------------------------------------------------
#define KV_PAD 68

__global__ __launch_bounds__(256)
void attn64(const float* __restrict__ Q, const float* __restrict__ Kt,
            const float* __restrict__ V, float* __restrict__ Out)
{
    __shared__ __align__(16) float Ksh[64][KV_PAD];
    __shared__ __align__(16) float Vsh[64][KV_PAD];
    __shared__ __align__(16) float Qsh[8][64];

    const int bh   = blockIdx.y;           // b*16 + h
    const int warp = threadIdx.x >> 5;
    const int lane = threadIdx.x & 31;
    const int srow = blockIdx.x * 8 + warp;

    const float* Qh = Q  + (size_t)bh * (SS * DD);
    const float* Kh = Kt + (size_t)bh * (SS * DD);
    const float* Vh = V  + (size_t)bh * (SS * DD);

    // load the 8 Q rows for this block (512 floats, 2 per thread)
    {
        int r = threadIdx.x >> 5;
        int d = (threadIdx.x & 31) * 2;
        float2 qv = *(const float2*)(Qh + (size_t)(blockIdx.x * 8 + r) * DD + d);
        Qsh[r][d] = qv.x;
        Qsh[r][d + 1] = qv.y;
    }

    float m = -1e30f, l = 0.f;
    float o[64];
#pragma unroll
    for (int d = 0; d < 64; d++) o[d] = 0.f;

    const float scale = 0.03125f;  // E^-0.5 = 1/32 (reference quirk: not D^-0.5)

    for (int t0 = 0; t0 < SS; t0 += 64) {
        __syncthreads();
        // load K,V chunk [64 x 64] cooperatively, coalesced float4 from gmem,
        // float4 into padded smem rows (aligned: row stride 272 B)
#pragma unroll
        for (int j = 0; j < 4; j++) {
            int flat = j * 1024 + threadIdx.x * 4;
            int r = flat >> 6, c = flat & 63;
            *(float4*)&Ksh[r][c] = *(const float4*)(Kh + (size_t)(t0 + r) * DD + c);
            *(float4*)&Vsh[r][c] = *(const float4*)(Vh + (size_t)(t0 + r) * DD + c);
        }
        __syncthreads();

        // scores for t = lane, lane+32 (float4 LDS, conflict-free)
        float s0 = 0.f, s1 = 0.f;
        const float4* qrow  = (const float4*)&Qsh[warp][0];
        const float4* krow0 = (const float4*)&Ksh[lane][0];
        const float4* krow1 = (const float4*)&Ksh[lane + 32][0];
#pragma unroll
        for (int d4 = 0; d4 < 16; d4++) {
            float4 q  = qrow[d4];
            float4 k0 = krow0[d4];
            float4 k1 = krow1[d4];
            s0 += q.x * k0.x + q.y * k0.y + q.z * k0.z + q.w * k0.w;
            s1 += q.x * k1.x + q.y * k1.y + q.z * k1.z + q.w * k1.w;
        }
        s0 *= scale;
        s1 *= scale;

        float mx = fmaxf(s0, s1);
#pragma unroll
        for (int off = 16; off; off >>= 1)
            mx = fmaxf(mx, __shfl_xor_sync(0xffffffffu, mx, off));
        float mnew = fmaxf(m, mx);
        float corr = __expf(m - mnew);
        float p0 = __expf(s0 - mnew);
        float p1 = __expf(s1 - mnew);
        float ps = p0 + p1;
#pragma unroll
        for (int off = 16; off; off >>= 1)
            ps += __shfl_xor_sync(0xffffffffu, ps, off);
        l = l * corr + ps;
        m = mnew;

        const float4* vrow0 = (const float4*)&Vsh[lane][0];
        const float4* vrow1 = (const float4*)&Vsh[lane + 32][0];
#pragma unroll
        for (int d4 = 0; d4 < 16; d4++) {
            float4 v0 = vrow0[d4];
            float4 v1 = vrow1[d4];
            o[d4 * 4 + 0] = o[d4 * 4 + 0] * corr + p0 * v0.x + p1 * v1.x;
            o[d4 * 4 + 1] = o[d4 * 4 + 1] * corr + p0 * v0.y + p1 * v1.y;
            o[d4 * 4 + 2] = o[d4 * 4 + 2] * corr + p0 * v0.z + p1 * v1.z;
            o[d4 * 4 + 3] = o[d4 * 4 + 3] * corr + p0 * v0.w + p1 * v1.w;
        }
    }

    // butterfly-reduce O partials across the warp (all lanes end with full sums)
#pragma unroll
    for (int d = 0; d < 64; d++) {
#pragma unroll
        for (int off = 16; off; off >>= 1)
            o[d] += __shfl_xor_sync(0xffffffffu, o[d], off);
    }

    // lane writes d = 2*lane, 2*lane+1; avoid dynamic register indexing
    float r0 = 0.f, r1 = 0.f;
#pragma unroll
    for (int d = 0; d < 64; d++) {
        if ((d >> 1) == lane) {
            if (d & 1) r1 = o[d]; else r0 = o[d];
        }
    }
    float inv = 1.f / l;
    int b = bh >> 4, h = bh & 15;
    float* op = Out + ((size_t)(b * SS + srow) * EE) + h * DD + lane * 2;
    float2 res;
    res.x = r0 * inv;
    res.y = r1 * inv;
    *(float2*)op = res;
}

// ---------------------------------------------------------------------------
// Launch: hidden -> Q,K,V (3 GEMMs) -> attention -> output GEMM (+bias)
// ---------------------------------------------------------------------------
extern "C" void kernel_launch(void* const* d_in, const int* in_sizes, int n_in,
                              void* d_out, int out_size)
{
    const float* hidden = (const float*)d_in[0];
    const float* w_q    = (const float*)d_in[1];
    const float* w_k    = (const float*)d_in[2];
    const float* w_v    = (const float*)d_in[3];
    const float* w_out  = (const float*)d_in[4];
    const float* b_out  = (const float*)d_in[5];
    float* out = (float*)d_out;

    float *q, *k, *v, *attn;
    cudaGetSymbolAddress((void**)&q, g_q);
    cudaGetSymbolAddress((void**)&k, g_k);
    cudaGetSymbolAddress((void**)&v, g_v);
    cudaGetSymbolAddress((void**)&attn, g_attn);

    dim3 gg(EE / 128, MM / 128);   // (8, 64)
    dim3 bb(256);

    sgemm128<<<gg, bb>>>(hidden, w_q, nullptr, q, MM, EE, EE);
    sgemm128<<<gg, bb>>>(hidden, w_k, nullptr, k, MM, EE, EE);
    sgemm128<<<gg, bb>>>(hidden, w_v, nullptr, v, MM, EE, EE);

    dim3 ga(SS / 8, BB * HH);      // (128, 128)
    attn64<<<ga, bb>>>(q, k, v, attn);

    sgemm128<<<gg, bb>>>(attn, w_out, b_out, out, MM, EE, EE);
}

// round 7
// speedup vs baseline: 1.2001x; 1.2001x over previous
#include <cuda_runtime.h>
#include <cuda_bf16.h>
#include <cstdint>
#include <math.h>

// Problem constants: B=8, S=1024, E=1024, H=16, D=64
#define BB 8
#define SS 1024
#define EE 1024
#define HH 16
#define DD 64
#define MM (BB * SS)          // 8192 rows for all GEMMs

// ---------------------------------------------------------------------------
// Scratch (allocation-free rule: __device__ globals)
// ---------------------------------------------------------------------------
__device__ float g_q[MM * EE];
__device__ float g_k[MM * EE];
__device__ float g_v[MM * EE];
__device__ __nv_bfloat16 g_ahi[MM * EE];   // split(hidden) hi
__device__ __nv_bfloat16 g_alo[MM * EE];   // split(hidden) lo
__device__ __nv_bfloat16 g_phi[MM * EE];   // split(attn out) hi
__device__ __nv_bfloat16 g_plo[MM * EE];   // split(attn out) lo
__device__ __nv_bfloat16 g_whi[EE * EE];   // split+transposed weight hi [N,K]
__device__ __nv_bfloat16 g_wlo[EE * EE];   // split+transposed weight lo [N,K]

// ---------------------------------------------------------------------------
// PTX helpers — all base-target (sm_80+) instructions only.
// ---------------------------------------------------------------------------
__device__ __forceinline__ uint32_t smem_to_u32(const void* p) {
    uint32_t a;
    asm("{ .reg .u64 t; cvta.to.shared.u64 t, %1; cvt.u32.u64 %0, t; }" : "=r"(a) : "l"(p));
    return a;
}
__device__ __forceinline__ void cpa16(uint32_t dst, const void* src) {
    asm volatile("cp.async.cg.shared.global [%0], [%1], 16;" :: "r"(dst), "l"(src));
}
#define CP_COMMIT() asm volatile("cp.async.commit_group;" ::: "memory")
#define CP_WAIT0()  asm volatile("cp.async.wait_group 0;" ::: "memory")
#define CP_WAIT1()  asm volatile("cp.async.wait_group 1;" ::: "memory")

#define LDSM4(r0, r1, r2, r3, addr) \
    asm volatile("ldmatrix.sync.aligned.m8n8.x4.shared.b16 {%0,%1,%2,%3}, [%4];" \
        : "=r"(r0), "=r"(r1), "=r"(r2), "=r"(r3) : "r"(addr))

#define MMA16816(c, a, b0, b1) \
    asm volatile("mma.sync.aligned.m16n8k16.row.col.f32.bf16.bf16.f32 " \
        "{%0,%1,%2,%3}, {%4,%5,%6,%7}, {%8,%9}, {%0,%1,%2,%3};" \
        : "+f"((c)[0]), "+f"((c)[1]), "+f"((c)[2]), "+f"((c)[3]) \
        : "r"((a)[0]), "r"((a)[1]), "r"((a)[2]), "r"((a)[3]), "r"(b0), "r"(b1))

// ---------------------------------------------------------------------------
// split_fp32: x -> (hi, lo) bf16, elementwise, 4 per thread
// ---------------------------------------------------------------------------
__global__ void split_fp32(const float4* __restrict__ X,
                           __nv_bfloat162* __restrict__ hi,
                           __nv_bfloat162* __restrict__ lo, int n4)
{
    int i = blockIdx.x * blockDim.x + threadIdx.x;
    if (i >= n4) return;
    float4 x = X[i];
    __nv_bfloat16 h0 = __float2bfloat16(x.x), h1 = __float2bfloat16(x.y);
    __nv_bfloat16 h2 = __float2bfloat16(x.z), h3 = __float2bfloat16(x.w);
    __nv_bfloat16 l0 = __float2bfloat16(x.x - __bfloat162float(h0));
    __nv_bfloat16 l1 = __float2bfloat16(x.y - __bfloat162float(h1));
    __nv_bfloat16 l2 = __float2bfloat16(x.z - __bfloat162float(h2));
    __nv_bfloat16 l3 = __float2bfloat16(x.w - __bfloat162float(h3));
    hi[2 * i]     = __halves2bfloat162(h0, h1);
    hi[2 * i + 1] = __halves2bfloat162(h2, h3);
    lo[2 * i]     = __halves2bfloat162(l0, l1);
    lo[2 * i + 1] = __halves2bfloat162(l2, l3);
}

// ---------------------------------------------------------------------------
// splitT_w: W[K,N] fp32 -> hi/lo [N,K] bf16 (transpose + split), 32x32 tiles
// ---------------------------------------------------------------------------
__global__ void splitT_w(const float* __restrict__ W,
                         __nv_bfloat16* __restrict__ hi, __nv_bfloat16* __restrict__ lo)
{
    __shared__ float t[32][33];
    int n0 = blockIdx.x * 32, k0 = blockIdx.y * 32;
    int tx = threadIdx.x, ty = threadIdx.y;
#pragma unroll
    for (int i = 0; i < 32; i += 8)
        t[ty + i][tx] = W[(size_t)(k0 + ty + i) * EE + n0 + tx];
    __syncthreads();
#pragma unroll
    for (int i = 0; i < 32; i += 8) {
        float v = t[tx][ty + i];
        __nv_bfloat16 h = __float2bfloat16(v);
        size_t o = (size_t)(n0 + ty + i) * EE + k0 + tx;
        hi[o] = h;
        lo[o] = __float2bfloat16(v - __bfloat162float(h));
    }
}

// ---------------------------------------------------------------------------
// gemm_mma: C[8192,1024] = split-bf16(A[M,K]) @ split-bf16(W' [N,K]) (+bias)
// CTA 128x128, K-chunk 64 bf16; 8 warps (2Mx4N), warp tile 64x32.
// Smem rows padded to 72 bf16 (144 B); cp.async double-buffer; ldmatrix +
// mma.sync m16n8k16 bf16, fp32 accum. 3 split terms: hh + hl + lh.
// ---------------------------------------------------------------------------
#define ROWP   72                       // padded row, bf16 elements
#define TILE_B (128 * ROWP * 2)         // 18432 B per tile
#define STAGE_B (4 * TILE_B)            // Ah, Al, Wh, Wl
#define NCHUNK 16                       // K=1024 / 64

__global__ __launch_bounds__(256, 1)
void gemm_mma(const __nv_bfloat16* __restrict__ Ahi, const __nv_bfloat16* __restrict__ Alo,
              const __nv_bfloat16* __restrict__ Whi, const __nv_bfloat16* __restrict__ Wlo,
              const float* __restrict__ bias, float* __restrict__ C)
{
    extern __shared__ char smem[];
    const uint32_t sb = smem_to_u32(smem);
    const int tid = threadIdx.x, wid = tid >> 5, lane = tid & 31;
    const int bm = blockIdx.y * 128, bn = blockIdx.x * 128;
    const int N = EE;

    // global load mapping: row = tid/2 (0..127), 4 consecutive 16B per thread
    const int grow = tid >> 1;
    const int gc16 = (tid & 1) * 4;       // 16B-column base (0 or 4; 8 per row)
    const char* srcAh = (const char*)(Ahi + (size_t)(bm + grow) * EE) + gc16 * 16;
    const char* srcAl = (const char*)(Alo + (size_t)(bm + grow) * EE) + gc16 * 16;
    const char* srcWh = (const char*)(Whi + (size_t)(bn + grow) * EE) + gc16 * 16;
    const char* srcWl = (const char*)(Wlo + (size_t)(bn + grow) * EE) + gc16 * 16;
    const uint32_t dstRow = (uint32_t)grow * 144u + (uint32_t)gc16 * 16u;

    // warp layout: wm in {0,1} (64 M rows), wn in {0..3} (32 N rows)
    const int wmOff = (wid >> 2) * 64;
    const int wnOff = (wid & 3) * 32;
    const int laneRow = lane & 15;
    const uint32_t laneKB = (uint32_t)(lane >> 4) * 16u;   // k-half byte offset

    float acc[4][4][4];
#pragma unroll
    for (int i = 0; i < 4; i++)
#pragma unroll
        for (int j = 0; j < 4; j++)
#pragma unroll
            for (int r = 0; r < 4; r++) acc[i][j][r] = 0.f;

    // ---- stage loader (16 cp.async of 16B per thread) ----
    auto load_stage = [&](int c, int buf) {
        const uint32_t st = sb + (uint32_t)buf * STAGE_B + dstRow;
        const size_t srcOff = (size_t)c * 128;
#pragma unroll
        for (int j = 0; j < 4; j++) {
            uint32_t d = st + (uint32_t)j * 16u;
            cpa16(d,              srcAh + srcOff + j * 16);
            cpa16(d + TILE_B,     srcAl + srcOff + j * 16);
            cpa16(d + 2 * TILE_B, srcWh + srcOff + j * 16);
            cpa16(d + 3 * TILE_B, srcWl + srcOff + j * 16);
        }
        CP_COMMIT();
    };

    load_stage(0, 0);

    for (int c = 0; c < NCHUNK; c++) {
        const int buf = c & 1;
        if (c + 1 < NCHUNK) { load_stage(c + 1, buf ^ 1); CP_WAIT1(); }
        else                { CP_WAIT0(); }
        __syncthreads();

        const uint32_t st = sb + (uint32_t)buf * STAGE_B;
        const uint32_t aB = st + (uint32_t)(wmOff + laneRow) * 144u + laneKB;
        const uint32_t bB = st + 2 * TILE_B + (uint32_t)(wnOff + laneRow) * 144u + laneKB;

#pragma unroll
        for (int kk = 0; kk < 4; kk++) {
            uint32_t ah[4][4], al[4][4], bh[2][4], bl[2][4];
#pragma unroll
            for (int i = 0; i < 4; i++) {
                uint32_t a = aB + (uint32_t)i * 2304u + (uint32_t)kk * 32u;
                LDSM4(ah[i][0], ah[i][1], ah[i][2], ah[i][3], a);
                LDSM4(al[i][0], al[i][1], al[i][2], al[i][3], a + TILE_B);
            }
#pragma unroll
            for (int j2 = 0; j2 < 2; j2++) {
                uint32_t b = bB + (uint32_t)j2 * 2304u + (uint32_t)kk * 32u;
                LDSM4(bh[j2][0], bh[j2][1], bh[j2][2], bh[j2][3], b);
                LDSM4(bl[j2][0], bl[j2][1], bl[j2][2], bl[j2][3], b + TILE_B);
            }
#pragma unroll
            for (int i = 0; i < 4; i++)
#pragma unroll
                for (int j = 0; j < 4; j++) {
                    const int j2 = j >> 1, s = j & 1;
                    MMA16816(acc[i][j], ah[i], bh[j2][s], bh[j2][s + 2]);   // hh
                    MMA16816(acc[i][j], ah[i], bl[j2][s], bl[j2][s + 2]);   // hl
                    MMA16816(acc[i][j], al[i], bh[j2][s], bh[j2][s + 2]);   // lh
                }
        }
        __syncthreads();
    }

    // ---- epilogue: C frag c0,c1 -> row m+t/4, cols n+2(t%4); c2,c3 -> row +8
    const int mrow = bm + wmOff + (lane >> 2);
    const int ncol = bn + wnOff + (lane & 3) * 2;
#pragma unroll
    for (int j = 0; j < 4; j++) {
        float b0 = 0.f, b1 = 0.f;
        if (bias) {
            const float2 bv = *(const float2*)(bias + ncol + j * 8);
            b0 = bv.x; b1 = bv.y;
        }
#pragma unroll
        for (int i = 0; i < 4; i++) {
            float2 v0, v1;
            v0.x = acc[i][j][0] + b0; v0.y = acc[i][j][1] + b1;
            v1.x = acc[i][j][2] + b0; v1.y = acc[i][j][3] + b1;
            *(float2*)(C + (size_t)(mrow + i * 16) * N + ncol + j * 8)     = v0;
            *(float2*)(C + (size_t)(mrow + i * 16 + 8) * N + ncol + j * 8) = v1;
        }
    }
}

// ---------------------------------------------------------------------------
// Attention: flash-style, 1 warp per query row; head slabs contiguous due to
// the reference's raw-reshape quirk. Writes split-bf16 output directly.
// ---------------------------------------------------------------------------
#define KV_PAD 68

__global__ __launch_bounds__(256)
void attn64(const float* __restrict__ Q, const float* __restrict__ Kt,
            const float* __restrict__ V,
            __nv_bfloat16* __restrict__ Phi, __nv_bfloat16* __restrict__ Plo)
{
    __shared__ __align__(16) float Ksh[64][KV_PAD];
    __shared__ __align__(16) float Vsh[64][KV_PAD];
    __shared__ __align__(16) float Qsh[8][64];

    const int bh   = blockIdx.y;           // b*16 + h
    const int warp = threadIdx.x >> 5;
    const int lane = threadIdx.x & 31;
    const int srow = blockIdx.x * 8 + warp;

    const float* Qh = Q  + (size_t)bh * (SS * DD);
    const float* Kh = Kt + (size_t)bh * (SS * DD);
    const float* Vh = V  + (size_t)bh * (SS * DD);

    {
        int r = threadIdx.x >> 5;
        int d = (threadIdx.x & 31) * 2;
        float2 qv = *(const float2*)(Qh + (size_t)(blockIdx.x * 8 + r) * DD + d);
        Qsh[r][d] = qv.x;
        Qsh[r][d + 1] = qv.y;
    }

    float m = -1e30f, l = 0.f;
    float o[64];
#pragma unroll
    for (int d = 0; d < 64; d++) o[d] = 0.f;

    const float scale = 0.03125f;  // E^-0.5 (reference quirk)

    for (int t0 = 0; t0 < SS; t0 += 64) {
        __syncthreads();
#pragma unroll
        for (int j = 0; j < 4; j++) {
            int flat = j * 1024 + threadIdx.x * 4;
            int r = flat >> 6, c = flat & 63;
            *(float4*)&Ksh[r][c] = *(const float4*)(Kh + (size_t)(t0 + r) * DD + c);
            *(float4*)&Vsh[r][c] = *(const float4*)(Vh + (size_t)(t0 + r) * DD + c);
        }
        __syncthreads();

        float s0 = 0.f, s1 = 0.f;
        const float4* qrow  = (const float4*)&Qsh[warp][0];
        const float4* krow0 = (const float4*)&Ksh[lane][0];
        const float4* krow1 = (const float4*)&Ksh[lane + 32][0];
#pragma unroll
        for (int d4 = 0; d4 < 16; d4++) {
            float4 q  = qrow[d4];
            float4 k0 = krow0[d4];
            float4 k1 = krow1[d4];
            s0 += q.x * k0.x + q.y * k0.y + q.z * k0.z + q.w * k0.w;
            s1 += q.x * k1.x + q.y * k1.y + q.z * k1.z + q.w * k1.w;
        }
        s0 *= scale;
        s1 *= scale;

        float mx = fmaxf(s0, s1);
#pragma unroll
        for (int off = 16; off; off >>= 1)
            mx = fmaxf(mx, __shfl_xor_sync(0xffffffffu, mx, off));
        float mnew = fmaxf(m, mx);
        float corr = __expf(m - mnew);
        float p0 = __expf(s0 - mnew);
        float p1 = __expf(s1 - mnew);
        float ps = p0 + p1;
#pragma unroll
        for (int off = 16; off; off >>= 1)
            ps += __shfl_xor_sync(0xffffffffu, ps, off);
        l = l * corr + ps;
        m = mnew;

        const float4* vrow0 = (const float4*)&Vsh[lane][0];
        const float4* vrow1 = (const float4*)&Vsh[lane + 32][0];
#pragma unroll
        for (int d4 = 0; d4 < 16; d4++) {
            float4 v0 = vrow0[d4];
            float4 v1 = vrow1[d4];
            o[d4 * 4 + 0] = o[d4 * 4 + 0] * corr + p0 * v0.x + p1 * v1.x;
            o[d4 * 4 + 1] = o[d4 * 4 + 1] * corr + p0 * v0.y + p1 * v1.y;
            o[d4 * 4 + 2] = o[d4 * 4 + 2] * corr + p0 * v0.z + p1 * v1.z;
            o[d4 * 4 + 3] = o[d4 * 4 + 3] * corr + p0 * v0.w + p1 * v1.w;
        }
    }

#pragma unroll
    for (int d = 0; d < 64; d++) {
#pragma unroll
        for (int off = 16; off; off >>= 1)
            o[d] += __shfl_xor_sync(0xffffffffu, o[d], off);
    }

    float r0 = 0.f, r1 = 0.f;
#pragma unroll
    for (int d = 0; d < 64; d++) {
        if ((d >> 1) == lane) {
            if (d & 1) r1 = o[d]; else r0 = o[d];
        }
    }
    float inv = 1.f / l;
    float rx = r0 * inv, ry = r1 * inv;
    int b = bh >> 4, h = bh & 15;
    size_t off = ((size_t)(b * SS + srow) * EE) + h * DD + lane * 2;

    __nv_bfloat16 hx = __float2bfloat16(rx), hy = __float2bfloat16(ry);
    *(__nv_bfloat162*)(Phi + off) = __halves2bfloat162(hx, hy);
    __nv_bfloat16 lx = __float2bfloat16(rx - __bfloat162float(hx));
    __nv_bfloat16 ly = __float2bfloat16(ry - __bfloat162float(hy));
    *(__nv_bfloat162*)(Plo + off) = __halves2bfloat162(lx, ly);
}

// ---------------------------------------------------------------------------
// Launch
// ---------------------------------------------------------------------------
extern "C" void kernel_launch(void* const* d_in, const int* in_sizes, int n_in,
                              void* d_out, int out_size)
{
    const float* hidden = (const float*)d_in[0];
    const float* w_q    = (const float*)d_in[1];
    const float* w_k    = (const float*)d_in[2];
    const float* w_v    = (const float*)d_in[3];
    const float* w_out  = (const float*)d_in[4];
    const float* b_out  = (const float*)d_in[5];
    float* out = (float*)d_out;

    float *q, *k, *v;
    __nv_bfloat16 *ahi, *alo, *phi, *plo, *whi, *wlo;
    cudaGetSymbolAddress((void**)&q, g_q);
    cudaGetSymbolAddress((void**)&k, g_k);
    cudaGetSymbolAddress((void**)&v, g_v);
    cudaGetSymbolAddress((void**)&ahi, g_ahi);
    cudaGetSymbolAddress((void**)&alo, g_alo);
    cudaGetSymbolAddress((void**)&phi, g_phi);
    cudaGetSymbolAddress((void**)&plo, g_plo);
    cudaGetSymbolAddress((void**)&whi, g_whi);
    cudaGetSymbolAddress((void**)&wlo, g_wlo);

    const int GSMEM = 2 * STAGE_B;   // 147456 B
    cudaFuncSetAttribute(gemm_mma, cudaFuncAttributeMaxDynamicSharedMemorySize, GSMEM);

    dim3 gw(32, 32), bw(32, 8);
    dim3 gg(EE / 128, MM / 128);          // (8, 64)

    // split A (hidden) once
    int n4 = MM * EE / 4;
    split_fp32<<<(n4 + 255) / 256, 256>>>((const float4*)hidden,
                                          (__nv_bfloat162*)ahi, (__nv_bfloat162*)alo, n4);

    splitT_w<<<gw, bw>>>(w_q, whi, wlo);
    gemm_mma<<<gg, 256, GSMEM>>>(ahi, alo, whi, wlo, nullptr, q);
    splitT_w<<<gw, bw>>>(w_k, whi, wlo);
    gemm_mma<<<gg, 256, GSMEM>>>(ahi, alo, whi, wlo, nullptr, k);
    splitT_w<<<gw, bw>>>(w_v, whi, wlo);
    gemm_mma<<<gg, 256, GSMEM>>>(ahi, alo, whi, wlo, nullptr, v);

    dim3 ga(SS / 8, BB * HH);             // (128, 128)
    attn64<<<ga, 256>>>(q, k, v, phi, plo);

    splitT_w<<<gw, bw>>>(w_out, whi, wlo);
    gemm_mma<<<gg, 256, GSMEM>>>(phi, plo, whi, wlo, b_out, out);
}